// round 7
// baseline (speedup 1.0000x reference)
#include <cuda_runtime.h>
#include <cuda_bf16.h>
#include <cuda_fp16.h>
#include <math.h>
#include <cstdint>

#define Bb 2
#define Ss 2048
#define Ee 2048
#define Hh 16
#define Dh 128
#define GK 6144          // packed K = 3 * 2048
#define GKC 192          // GK / 32 chunks

#define GSTAGE_BYTES 30720                      // A 128*80 + B 256*80
#define GEMM_SMEM_BYTES (4 * GSTAGE_BYTES)      // 122880

// ---------------- scratch (__device__ globals; no allocation allowed) -------
__device__ __nv_bfloat16 g_a_p[(size_t)Bb * Ss * GK];       // packed activations
__device__ __nv_bfloat16 g_wqkv_p[(size_t)3 * Ee * GK];     // packed Wqkv
__device__ __nv_bfloat16 g_wout_p[(size_t)Ee * GK];         // packed Wout
__device__ __half g_qp[(size_t)Bb * Hh * Ss * 256];         // q fp16 [qh|ql], roped+scaled
__device__ __half g_kp[(size_t)Bb * Hh * Ss * 256];         // k fp16 [kh|kl], roped
__device__ __half g_vt[(size_t)Bb * Hh * 2 * Dh * Ss];      // V^T fp16 planes [vh][vl]

__device__ __forceinline__ uint32_t smem_u32(const void* p) {
    uint32_t a;
    asm("{ .reg .u64 t; cvta.to.shared.u64 t, %1; cvt.u32.u64 %0, t; }"
        : "=r"(a) : "l"(p));
    return a;
}

// ---------------------------------------------------------------------------
// Packing: fp32 -> 3-term bf16 split along K.  A:[h|h|l]  B:[h|l|h]
// ---------------------------------------------------------------------------
__device__ __forceinline__ void split_bf16(float x, __nv_bfloat16& h, __nv_bfloat16& l) {
    h = __float2bfloat16(x);
    l = __float2bfloat16(x - __bfloat162float(h));
}

template <int ISA>
__global__ __launch_bounds__(256) void pack_kernel(
    const float* __restrict__ src, __nv_bfloat16* __restrict__ dst, int total4)
{
    int i = blockIdx.x * blockDim.x + threadIdx.x;
    if (i >= total4) return;
    int r = i >> 9;
    int k4 = (i & 511) * 4;
    float4 x = *(const float4*)(src + ((size_t)r << 11) + k4);
    __nv_bfloat16 h[4], l[4];
    split_bf16(x.x, h[0], l[0]); split_bf16(x.y, h[1], l[1]);
    split_bf16(x.z, h[2], l[2]); split_bf16(x.w, h[3], l[3]);
    size_t rb = (size_t)r * GK + k4;
    __nv_bfloat162 hp0 = {h[0], h[1]}, hp1 = {h[2], h[3]};
    __nv_bfloat162 lp0 = {l[0], l[1]}, lp1 = {l[2], l[3]};
    *(__nv_bfloat162*)(dst + rb + 0) = hp0; *(__nv_bfloat162*)(dst + rb + 2) = hp1;
    if (ISA) {
        *(__nv_bfloat162*)(dst + rb + 2048) = hp0; *(__nv_bfloat162*)(dst + rb + 2050) = hp1;
        *(__nv_bfloat162*)(dst + rb + 4096) = lp0; *(__nv_bfloat162*)(dst + rb + 4098) = lp1;
    } else {
        *(__nv_bfloat162*)(dst + rb + 2048) = lp0; *(__nv_bfloat162*)(dst + rb + 2050) = lp1;
        *(__nv_bfloat162*)(dst + rb + 4096) = hp0; *(__nv_bfloat162*)(dst + rb + 4098) = hp1;
    }
}

// ---------------------------------------------------------------------------
// mma helpers
// ---------------------------------------------------------------------------
__device__ __forceinline__ void mma_bf16(float* c, const uint32_t* a, const uint32_t* b) {
    asm volatile(
        "mma.sync.aligned.m16n8k16.row.col.f32.bf16.bf16.f32 "
        "{%0,%1,%2,%3}, {%4,%5,%6,%7}, {%8,%9}, {%0,%1,%2,%3};"
        : "+f"(c[0]), "+f"(c[1]), "+f"(c[2]), "+f"(c[3])
        : "r"(a[0]), "r"(a[1]), "r"(a[2]), "r"(a[3]), "r"(b[0]), "r"(b[1]));
}
__device__ __forceinline__ void mma_fp16(float* c, const uint32_t* a, const uint32_t* b) {
    asm volatile(
        "mma.sync.aligned.m16n8k16.row.col.f32.f16.f16.f32 "
        "{%0,%1,%2,%3}, {%4,%5,%6,%7}, {%8,%9}, {%0,%1,%2,%3};"
        : "+f"(c[0]), "+f"(c[1]), "+f"(c[2]), "+f"(c[3])
        : "r"(a[0]), "r"(a[1]), "r"(a[2]), "r"(a[3]), "r"(b[0]), "r"(b[1]));
}
__device__ __forceinline__ void ldsm_x4(uint32_t* r, uint32_t addr) {
    asm volatile("ldmatrix.sync.aligned.m8n8.x4.shared.b16 {%0,%1,%2,%3}, [%4];"
        : "=r"(r[0]), "=r"(r[1]), "=r"(r[2]), "=r"(r[3]) : "r"(addr));
}

// ---------------------------------------------------------------------------
// Projection GEMM v3: CTA tile 128x256, 8 warps (2M x 4N), warp tile 64x64.
// K-chunk 32, 4-stage cp.async, 80-byte row pitch (conflict-free ldsm).
// MODE 0: fp32 store.  MODE 1: QKV epilogue with fused rope + fp16 packing.
// ---------------------------------------------------------------------------
template <int MODE>
__global__ __launch_bounds__(256, 1) void gemm_mma(
    const __nv_bfloat16* __restrict__ A, const __nv_bfloat16* __restrict__ Bw,
    float* __restrict__ C, int Ncols)
{
    extern __shared__ __align__(16) uint32_t gsm[];
    const uint32_t sbase = smem_u32(gsm);

    const int tid = threadIdx.x;
    const int lane = tid & 31, w = tid >> 5;
    const int wm = w & 1, wn = w >> 1;
    const int mbase = blockIdx.y * 128, nbase = blockIdx.x * 256;

    float acc[4][8][4];
#pragma unroll
    for (int i = 0; i < 4; i++)
#pragma unroll
        for (int j = 0; j < 8; j++)
#pragma unroll
            for (int r = 0; r < 4; r++) acc[i][j][r] = 0.f;

    const int grow = tid >> 2, gseg = tid & 3;
    const __nv_bfloat16* Ag = A + (size_t)(mbase + grow) * GK + gseg * 8;
    const __nv_bfloat16* Bg = Bw + (size_t)(nbase + grow) * GK + gseg * 8;
    const size_t rstep = (size_t)64 * GK;
    const uint32_t dbA = (grow * 20 + gseg * 4) * 4;         // byte off in A part
    const uint32_t dbB = 10240 + dbA;                        // byte off in B part

#define ISSUE(c) do {                                                          \
    uint32_t st = sbase + ((c) & 3) * GSTAGE_BYTES;                            \
    const __nv_bfloat16* sA = Ag + (size_t)(c) * 32;                           \
    const __nv_bfloat16* sB = Bg + (size_t)(c) * 32;                           \
    asm volatile("cp.async.cg.shared.global [%0], [%1], 16;" :: "r"(st + dbA), "l"(sA)); \
    asm volatile("cp.async.cg.shared.global [%0], [%1], 16;" :: "r"(st + dbA + 5120), "l"(sA + rstep)); \
    asm volatile("cp.async.cg.shared.global [%0], [%1], 16;" :: "r"(st + dbB), "l"(sB)); \
    asm volatile("cp.async.cg.shared.global [%0], [%1], 16;" :: "r"(st + dbB + 5120), "l"(sB + rstep)); \
    asm volatile("cp.async.cg.shared.global [%0], [%1], 16;" :: "r"(st + dbB + 10240), "l"(sB + 2 * rstep)); \
    asm volatile("cp.async.cg.shared.global [%0], [%1], 16;" :: "r"(st + dbB + 15360), "l"(sB + 3 * rstep)); \
} while (0)
#define COMMIT() asm volatile("cp.async.commit_group;" ::: "memory")
#define WAITG2() asm volatile("cp.async.wait_group 2;" ::: "memory")

    ISSUE(0); COMMIT();
    ISSUE(1); COMMIT();
    ISSUE(2); COMMIT();

    const int lane8 = lane & 7;
    const uint32_t aAddr = (uint32_t)((wm * 64 + ((lane >> 3) & 1) * 8 + lane8) * 80
                                      + (lane >> 4) * 16);
    const uint32_t bAddr = (uint32_t)(10240 + (wn * 64 + (lane >> 4) * 8 + lane8) * 80
                                      + ((lane >> 3) & 1) * 16);

    for (int c = 0; c < GKC; c++) {
        WAITG2();
        __syncthreads();
        if (c + 3 < GKC) ISSUE(c + 3);
        COMMIT();

        const uint32_t st = sbase + (c & 3) * GSTAGE_BYTES;
#pragma unroll
        for (int ks = 0; ks < 2; ks++) {
            uint32_t a[4][4], b[4][4];
#pragma unroll
            for (int i = 0; i < 4; i++)
                ldsm_x4(a[i], st + aAddr + i * 16 * 80 + ks * 32);
#pragma unroll
            for (int np = 0; np < 4; np++)
                ldsm_x4(b[np], st + bAddr + np * 16 * 80 + ks * 32);
#pragma unroll
            for (int i = 0; i < 4; i++)
#pragma unroll
                for (int np = 0; np < 4; np++) {
                    mma_bf16(acc[i][np * 2 + 0], a[i], &b[np][0]);
                    mma_bf16(acc[i][np * 2 + 1], a[i], &b[np][2]);
                }
        }
    }

#pragma unroll
    for (int i = 0; i < 4; i++) {
        int m0 = mbase + wm * 64 + i * 16 + (lane >> 2);
#pragma unroll
        for (int j = 0; j < 8; j++) {
            int n0 = nbase + wn * 64 + j * 8 + (lane & 3) * 2;
            if constexpr (MODE == 0) {
                *(float2*)(C + (size_t)m0 * Ncols + n0) =
                    make_float2(acc[i][j][0], acc[i][j][1]);
                *(float2*)(C + (size_t)(m0 + 8) * Ncols + n0) =
                    make_float2(acc[i][j][2], acc[i][j][3]);
            } else {
                int mp = n0 / 768;
                int rr = n0 - mp * 768;
                int which = rr >> 8;
                int ccc = rr & 255;
                int hh = mp * 2 + (ccc >> 7);
                int dd = ccc & 127;
                int bb = m0 >> 11, ss = m0 & 2047;
                int bh2 = bb * Hh + hh;
                float v0 = acc[i][j][0], v1 = acc[i][j][1];
                float v2 = acc[i][j][2], v3 = acc[i][j][3];
                if (which == 2) {
                    size_t vb = ((size_t)bh2 * 2 * Dh + dd) * (size_t)Ss + ss;
                    const size_t PL = (size_t)Dh * Ss;
                    __half a0 = __float2half(v0);
                    g_vt[vb] = a0;
                    g_vt[vb + PL] = __float2half(v0 - __half2float(a0));
                    __half a1 = __float2half(v1);
                    g_vt[vb + Ss] = a1;
                    g_vt[vb + Ss + PL] = __float2half(v1 - __half2float(a1));
                    __half a2 = __float2half(v2);
                    g_vt[vb + 8] = a2;
                    g_vt[vb + 8 + PL] = __float2half(v2 - __half2float(a2));
                    __half a3 = __float2half(v3);
                    g_vt[vb + Ss + 8] = a3;
                    g_vt[vb + Ss + 8 + PL] = __float2half(v3 - __half2float(a3));
                } else {
                    if (dd < 32) {
                        int ir = dd >> 1;
                        float f = powf(10000.f, -(float)ir * 0.0625f);
                        float s1, c1, s2, c2;
                        sincosf((float)ss * f, &s1, &c1);
                        sincosf((float)(ss + 8) * f, &s2, &c2);
                        float t0 = v0 * c1 - v1 * s1; v1 = v1 * c1 + v0 * s1; v0 = t0;
                        t0 = v2 * c2 - v3 * s2; v3 = v3 * c2 + v2 * s2; v2 = t0;
                    }
                    if (which == 0) {
                        const float sc = 0.08838834764831845f;
                        v0 *= sc; v1 *= sc; v2 *= sc; v3 *= sc;
                    }
                    __half* P = (which == 0) ? g_qp : g_kp;
                    size_t rb = ((size_t)bh2 * Ss + ss) * 256 + dd;
                    __half h0 = __float2half(v0), h1 = __float2half(v1);
                    __half h2 = __float2half(v2), h3 = __float2half(v3);
                    __half l0 = __float2half(v0 - __half2float(h0));
                    __half l1 = __float2half(v1 - __half2float(h1));
                    __half l2 = __float2half(v2 - __half2float(h2));
                    __half l3 = __float2half(v3 - __half2float(h3));
                    *(__half2*)(P + rb) = __halves2half2(h0, h1);
                    *(__half2*)(P + rb + 128) = __halves2half2(l0, l1);
                    *(__half2*)(P + rb + 8 * 256) = __halves2half2(h2, h3);
                    *(__half2*)(P + rb + 8 * 256 + 128) = __halves2half2(l2, l3);
                }
            }
        }
    }
}

// ---------------------------------------------------------------------------
// Tensor-core flash attention (unchanged from R6).
// ---------------------------------------------------------------------------
#define ATTN3_SMEM 154624

__global__ __launch_bounds__(256, 1) void attn3(
    const __half* __restrict__ qp, const __half* __restrict__ kp,
    const __half* __restrict__ vt)
{
    extern __shared__ char sm3[];
    const uint32_t sb = smem_u32(sm3);
    const uint32_t Qs = sb;
    const uint32_t Ks = sb + 67584;
    const uint32_t Vs = sb + 101376;
    const uint32_t Ps = sb + 136192;
    char* PsC = sm3 + 136192;

    const int qb = (int)gridDim.x - 1 - (int)blockIdx.x;
    const int h = blockIdx.y, b = blockIdx.z;
    const int bh = b * Hh + h;
    const int tid = threadIdx.x, lane = tid & 31, w = tid >> 5;
    const int qbase = qb * 128;

    {
        const __half* qg = qp + ((size_t)bh * Ss + qbase) * 256;
#pragma unroll
        for (int t = 0; t < 16; t++) {
            int u = tid + t * 256;
            int r = u >> 5, sg = u & 31;
            uint32_t dst = Qs + r * 528 + sg * 16;
            asm volatile("cp.async.cg.shared.global [%0], [%1], 16;"
                         :: "r"(dst), "l"(qg + r * 256 + sg * 8));
        }
        asm volatile("cp.async.commit_group;" ::: "memory");
    }

    float O[16][4];
#pragma unroll
    for (int i = 0; i < 16; i++)
#pragma unroll
        for (int r = 0; r < 4; r++) O[i][r] = 0.f;
    float m[2] = {-1e30f, -1e30f}, l[2] = {0.f, 0.f};

    const uint32_t aQ = Qs + (w * 16 + (lane & 15)) * 528 + (lane >> 4) * 16;
    const uint32_t bK = Ks + ((lane >> 4) * 8 + (lane & 7)) * 528 + ((lane >> 3) & 1) * 16;
    const uint32_t aP = Ps + (w * 16 + (lane & 15)) * 144 + (lane >> 4) * 16;
    const uint32_t bV = Vs + ((lane >> 4) * 8 + (lane & 7)) * 272 + ((lane >> 3) & 1) * 16;

    const int ntiles = 2 * qb + 2;
    for (int t = 0; t < ntiles; t++) {
        const int j0 = t * 64;
        __syncthreads();
        {
            const __half* kg = kp + ((size_t)bh * Ss + j0) * 256;
#pragma unroll
            for (int tt = 0; tt < 8; tt++) {
                int u = tid + tt * 256;
                int r = u >> 5, sg = u & 31;
                uint32_t dst = Ks + r * 528 + sg * 16;
                asm volatile("cp.async.cg.shared.global [%0], [%1], 16;"
                             :: "r"(dst), "l"(kg + r * 256 + sg * 8));
            }
        }
        {
            const __half* vg = vt + (size_t)bh * 2 * Dh * Ss + j0;
#pragma unroll
            for (int tt = 0; tt < 8; tt++) {
                int u = tid + tt * 256;
                int pd = u >> 3, sg = u & 7;
                int pl = pd >> 7, d = pd & 127;
                uint32_t dst = Vs + d * 272 + pl * 128 + sg * 16;
                asm volatile("cp.async.cg.shared.global [%0], [%1], 16;"
                             :: "r"(dst), "l"(vg + (size_t)pd * Ss + sg * 8));
            }
        }
        asm volatile("cp.async.commit_group;" ::: "memory");
        asm volatile("cp.async.wait_group 0;" ::: "memory");
        __syncthreads();

        float s[8][4];
#pragma unroll
        for (int nt = 0; nt < 8; nt++)
#pragma unroll
            for (int r = 0; r < 4; r++) s[nt][r] = 0.f;
#pragma unroll
        for (int pass = 0; pass < 3; pass++) {
            const uint32_t ao = (pass == 2) ? 256u : 0u;
            const uint32_t bo = (pass == 1) ? 256u : 0u;
#pragma unroll
            for (int c = 0; c < 8; c++) {
                uint32_t a[4];
                ldsm_x4(a, aQ + ao + c * 32);
#pragma unroll
                for (int np = 0; np < 4; np++) {
                    uint32_t bf[4];
                    ldsm_x4(bf, bK + bo + c * 32 + np * (16 * 528));
                    mma_fp16(s[np * 2 + 0], a, &bf[0]);
                    mma_fp16(s[np * 2 + 1], a, &bf[2]);
                }
            }
        }

        if (t >= ntiles - 2) {
#pragma unroll
            for (int nt = 0; nt < 8; nt++)
#pragma unroll
                for (int r = 0; r < 4; r++) {
                    int grow2 = qbase + w * 16 + (lane >> 2) + (r >> 1) * 8;
                    int gcol = j0 + nt * 8 + (lane & 3) * 2 + (r & 1);
                    if (gcol > grow2) s[nt][r] = -1e9f;
                }
        }

        float corr[2];
#pragma unroll
        for (int hh = 0; hh < 2; hh++) {
            float cm = -1e30f;
#pragma unroll
            for (int nt = 0; nt < 8; nt++)
                cm = fmaxf(cm, fmaxf(s[nt][hh * 2], s[nt][hh * 2 + 1]));
            cm = fmaxf(cm, __shfl_xor_sync(0xffffffffu, cm, 1));
            cm = fmaxf(cm, __shfl_xor_sync(0xffffffffu, cm, 2));
            float mn = fmaxf(m[hh], cm);
            corr[hh] = __expf(m[hh] - mn);
            m[hh] = mn;
            float ps = 0.f;
            int prow = w * 16 + (lane >> 2) + hh * 8;
#pragma unroll
            for (int nt = 0; nt < 8; nt++) {
                float p0 = __expf(s[nt][hh * 2] - mn);
                float p1 = __expf(s[nt][hh * 2 + 1] - mn);
                ps += p0 + p1;
                *(__half2*)(PsC + prow * 144 + (nt * 8 + (lane & 3) * 2) * 2) =
                    __floats2half2_rn(p0, p1);
            }
            ps += __shfl_xor_sync(0xffffffffu, ps, 1);
            ps += __shfl_xor_sync(0xffffffffu, ps, 2);
            l[hh] = l[hh] * corr[hh] + ps;
        }
#pragma unroll
        for (int i = 0; i < 16; i++) {
            O[i][0] *= corr[0]; O[i][1] *= corr[0];
            O[i][2] *= corr[1]; O[i][3] *= corr[1];
        }
        __syncthreads();

#pragma unroll
        for (int c = 0; c < 4; c++) {
            uint32_t a[4];
            ldsm_x4(a, aP + c * 32);
#pragma unroll
            for (int pass = 0; pass < 2; pass++) {
                const uint32_t bo = pass * 128u;
#pragma unroll
                for (int np = 0; np < 8; np++) {
                    uint32_t bf[4];
                    ldsm_x4(bf, bV + bo + c * 32 + np * (16 * 272));
                    mma_fp16(O[np * 2 + 0], a, &bf[0]);
                    mma_fp16(O[np * 2 + 1], a, &bf[2]);
                }
            }
        }
    }

    float inv0 = 1.f / l[0], inv1 = 1.f / l[1];
#pragma unroll
    for (int nt = 0; nt < 16; nt++) {
        int col = h * 128 + nt * 8 + (lane & 3) * 2;
#pragma unroll
        for (int hh = 0; hh < 2; hh++) {
            float inv = hh ? inv1 : inv0;
            float o0 = O[nt][hh * 2] * inv;
            float o1 = O[nt][hh * 2 + 1] * inv;
            int srow = qbase + w * 16 + (lane >> 2) + hh * 8;
            size_t rb = ((size_t)(b * Ss + srow)) * GK + col;
            __nv_bfloat16 h0, l0b, h1, l1b;
            split_bf16(o0, h0, l0b);
            split_bf16(o1, h1, l1b);
            __nv_bfloat162 hp = {h0, h1}, lp = {l0b, l1b};
            *(__nv_bfloat162*)(g_a_p + rb) = hp;
            *(__nv_bfloat162*)(g_a_p + rb + 2048) = hp;
            *(__nv_bfloat162*)(g_a_p + rb + 4096) = lp;
        }
    }
}

// ---------------------------------------------------------------------------
extern "C" void kernel_launch(void* const* d_in, const int* in_sizes, int n_in,
                              void* d_out, int out_size)
{
    const float* hidden = (const float*)d_in[0];
    const float* wqkv   = (const float*)d_in[1];
    const float* wout   = (const float*)d_in[2];
    float* out = (float*)d_out;

    __nv_bfloat16 *pap, *pwqkv, *pwout;
    __half *pqp, *pkp, *pvt;
    cudaGetSymbolAddress((void**)&pap,   g_a_p);
    cudaGetSymbolAddress((void**)&pwqkv, g_wqkv_p);
    cudaGetSymbolAddress((void**)&pwout, g_wout_p);
    cudaGetSymbolAddress((void**)&pqp,   g_qp);
    cudaGetSymbolAddress((void**)&pkp,   g_kp);
    cudaGetSymbolAddress((void**)&pvt,   g_vt);

    cudaFuncSetAttribute(gemm_mma<0>, cudaFuncAttributeMaxDynamicSharedMemorySize,
                         GEMM_SMEM_BYTES);
    cudaFuncSetAttribute(gemm_mma<1>, cudaFuncAttributeMaxDynamicSharedMemorySize,
                         GEMM_SMEM_BYTES);
    cudaFuncSetAttribute(attn3, cudaFuncAttributeMaxDynamicSharedMemorySize,
                         ATTN3_SMEM);

    // Pack weights + activations (bf16 3-term split)
    {
        int t4 = (3 * Ee * Ee) / 4;
        pack_kernel<0><<<(t4 + 255) / 256, 256>>>(wqkv, pwqkv, t4);
        t4 = (Ee * Ee) / 4;
        pack_kernel<0><<<(t4 + 255) / 256, 256>>>(wout, pwout, t4);
        t4 = (Bb * Ss * Ee) / 4;
        pack_kernel<1><<<(t4 + 255) / 256, 256>>>(hidden, pap, t4);
    }
    // 1) QKV projection + fused rope/scale/fp16-pack epilogue
    {
        dim3 grid(3 * Ee / 256, Bb * Ss / 128);  // (24, 32)
        gemm_mma<1><<<grid, 256, GEMM_SMEM_BYTES>>>(pap, pwqkv, nullptr, 0);
    }
    // 2) Tensor-core flash attention -> bf16 A-pack in g_a_p
    {
        dim3 grid(Ss / 128, Hh, Bb);  // (16,16,2)
        attn3<<<grid, 256, ATTN3_SMEM>>>(pqp, pkp, pvt);
    }
    // 3) Output projection
    {
        dim3 grid(Ee / 256, Bb * Ss / 128);  // (8, 32)
        gemm_mma<0><<<grid, 256, GEMM_SMEM_BYTES>>>(pap, pwout, out, Ee);
    }
}

// round 8
// speedup vs baseline: 1.2518x; 1.2518x over previous
#include <cuda_runtime.h>
#include <cuda_bf16.h>
#include <cuda_fp16.h>
#include <math.h>
#include <cstdint>

#define Bb 2
#define Ss 2048
#define Ee 2048
#define Hh 16
#define Dh 128
#define GK 6144          // packed K = 3 * 2048
#define GKC64 96         // GK / 64 chunks

#define GSTAGE_BYTES 36864                      // (A 128 + B 128 rows) * 144 B
#define GEMM_SMEM_BYTES (3 * GSTAGE_BYTES)      // 110592 -> 2 CTAs/SM

// ---------------- scratch (__device__ globals; no allocation allowed) -------
__device__ __nv_bfloat16 g_a_p[(size_t)Bb * Ss * GK];       // packed activations
__device__ __nv_bfloat16 g_wqkv_p[(size_t)3 * Ee * GK];     // packed Wqkv
__device__ __nv_bfloat16 g_wout_p[(size_t)Ee * GK];         // packed Wout
__device__ __half g_qp[(size_t)Bb * Hh * Ss * 256];         // q fp16 [qh|ql], roped+scaled
__device__ __half g_kp[(size_t)Bb * Hh * Ss * 256];         // k fp16 [kh|kl], roped
__device__ __half g_vt[(size_t)Bb * Hh * 2 * Dh * Ss];      // V^T fp16 planes [vh][vl]
__device__ float g_rope[(size_t)Ss * 16 * 2];               // (cos,sin) per (s, i)

__device__ __forceinline__ uint32_t smem_u32(const void* p) {
    uint32_t a;
    asm("{ .reg .u64 t; cvta.to.shared.u64 t, %1; cvt.u32.u64 %0, t; }"
        : "=r"(a) : "l"(p));
    return a;
}

// ---------------------------------------------------------------------------
// Rope table init: g_rope[(s*16+i)] = (cos(s*w_i), sin(s*w_i))
// ---------------------------------------------------------------------------
__global__ void rope_init()
{
    int idx = blockIdx.x * blockDim.x + threadIdx.x;   // Ss*16
    int i = idx & 15, s = idx >> 4;
    float f = powf(10000.f, -(float)i * 0.0625f);
    float sn, cs;
    sincosf((float)s * f, &sn, &cs);
    *(float2*)&g_rope[(size_t)idx * 2] = make_float2(cs, sn);
}

// ---------------------------------------------------------------------------
// Packing: fp32 -> 3-term bf16 split along K.  A:[h|h|l]  B:[h|l|h]
// ---------------------------------------------------------------------------
__device__ __forceinline__ void split_bf16(float x, __nv_bfloat16& h, __nv_bfloat16& l) {
    h = __float2bfloat16(x);
    l = __float2bfloat16(x - __bfloat162float(h));
}

template <int ISA>
__global__ __launch_bounds__(256) void pack_kernel(
    const float* __restrict__ src, __nv_bfloat16* __restrict__ dst, int total4)
{
    int i = blockIdx.x * blockDim.x + threadIdx.x;
    if (i >= total4) return;
    int r = i >> 9;
    int k4 = (i & 511) * 4;
    float4 x = *(const float4*)(src + ((size_t)r << 11) + k4);
    __nv_bfloat16 h[4], l[4];
    split_bf16(x.x, h[0], l[0]); split_bf16(x.y, h[1], l[1]);
    split_bf16(x.z, h[2], l[2]); split_bf16(x.w, h[3], l[3]);
    size_t rb = (size_t)r * GK + k4;
    __nv_bfloat162 hp0 = {h[0], h[1]}, hp1 = {h[2], h[3]};
    __nv_bfloat162 lp0 = {l[0], l[1]}, lp1 = {l[2], l[3]};
    *(__nv_bfloat162*)(dst + rb + 0) = hp0; *(__nv_bfloat162*)(dst + rb + 2) = hp1;
    if (ISA) {
        *(__nv_bfloat162*)(dst + rb + 2048) = hp0; *(__nv_bfloat162*)(dst + rb + 2050) = hp1;
        *(__nv_bfloat162*)(dst + rb + 4096) = lp0; *(__nv_bfloat162*)(dst + rb + 4098) = lp1;
    } else {
        *(__nv_bfloat162*)(dst + rb + 2048) = lp0; *(__nv_bfloat162*)(dst + rb + 2050) = lp1;
        *(__nv_bfloat162*)(dst + rb + 4096) = hp0; *(__nv_bfloat162*)(dst + rb + 4098) = hp1;
    }
}

// ---------------------------------------------------------------------------
// mma helpers
// ---------------------------------------------------------------------------
__device__ __forceinline__ void mma_bf16(float* c, const uint32_t* a, const uint32_t* b) {
    asm volatile(
        "mma.sync.aligned.m16n8k16.row.col.f32.bf16.bf16.f32 "
        "{%0,%1,%2,%3}, {%4,%5,%6,%7}, {%8,%9}, {%0,%1,%2,%3};"
        : "+f"(c[0]), "+f"(c[1]), "+f"(c[2]), "+f"(c[3])
        : "r"(a[0]), "r"(a[1]), "r"(a[2]), "r"(a[3]), "r"(b[0]), "r"(b[1]));
}
__device__ __forceinline__ void mma_fp16(float* c, const uint32_t* a, const uint32_t* b) {
    asm volatile(
        "mma.sync.aligned.m16n8k16.row.col.f32.f16.f16.f32 "
        "{%0,%1,%2,%3}, {%4,%5,%6,%7}, {%8,%9}, {%0,%1,%2,%3};"
        : "+f"(c[0]), "+f"(c[1]), "+f"(c[2]), "+f"(c[3])
        : "r"(a[0]), "r"(a[1]), "r"(a[2]), "r"(a[3]), "r"(b[0]), "r"(b[1]));
}
__device__ __forceinline__ void ldsm_x4(uint32_t* r, uint32_t addr) {
    asm volatile("ldmatrix.sync.aligned.m8n8.x4.shared.b16 {%0,%1,%2,%3}, [%4];"
        : "=r"(r[0]), "=r"(r[1]), "=r"(r[2]), "=r"(r[3]) : "r"(addr));
}

// ---------------------------------------------------------------------------
// Projection GEMM: CTA 128x128, 8 warps (2M x 4N), warp tile 64x32.
// K-chunk 64, 3-stage cp.async (96 barriers instead of 192), 144 B row pitch
// (ldmatrix rows hit distinct 16B banks: r*144 mod 128 = 16*r).
// MODE 0: fp32 store.  MODE 1: QKV epilogue, fused rope (table) + fp16 pack.
// ---------------------------------------------------------------------------
template <int MODE>
__global__ __launch_bounds__(256, 2) void gemm_mma(
    const __nv_bfloat16* __restrict__ A, const __nv_bfloat16* __restrict__ Bw,
    float* __restrict__ C, int Ncols)
{
    extern __shared__ __align__(16) uint32_t gsm[];
    const uint32_t sbase = smem_u32(gsm);

    const int tid = threadIdx.x;
    const int lane = tid & 31, w = tid >> 5;
    const int wm = w & 1, wn = w >> 1;
    const int mbase = blockIdx.y * 128, nbase = blockIdx.x * 128;

    float acc[4][4][4];
#pragma unroll
    for (int i = 0; i < 4; i++)
#pragma unroll
        for (int j = 0; j < 4; j++)
#pragma unroll
            for (int r = 0; r < 4; r++) acc[i][j][r] = 0.f;

    // producer mapping: row = (tid>>3) + j*32, seg = tid&7 (16 B each)
    const int grow = tid >> 3, gseg = tid & 7;
    const __nv_bfloat16* Ag = A + (size_t)(mbase + grow) * GK + gseg * 8;
    const __nv_bfloat16* Bg = Bw + (size_t)(nbase + grow) * GK + gseg * 8;
    const size_t rstep32 = (size_t)32 * GK;
    const uint32_t dbase = grow * 144 + gseg * 16;

#define ISSUE(c, str) do {                                                     \
    uint32_t st = sbase + (uint32_t)(str) * GSTAGE_BYTES;                      \
    const __nv_bfloat16* sA = Ag + (size_t)(c) * 64;                           \
    const __nv_bfloat16* sB = Bg + (size_t)(c) * 64;                           \
    _Pragma("unroll")                                                          \
    for (int j = 0; j < 4; j++) {                                              \
        asm volatile("cp.async.cg.shared.global [%0], [%1], 16;"               \
            :: "r"(st + dbase + j * (32 * 144)), "l"(sA + j * rstep32));       \
        asm volatile("cp.async.cg.shared.global [%0], [%1], 16;"               \
            :: "r"(st + 18432 + dbase + j * (32 * 144)), "l"(sB + j * rstep32)); \
    }                                                                          \
} while (0)
#define COMMIT() asm volatile("cp.async.commit_group;" ::: "memory")
#define WAITG1() asm volatile("cp.async.wait_group 1;" ::: "memory")

    ISSUE(0, 0); COMMIT();
    ISSUE(1, 1); COMMIT();

    const int lane8 = lane & 7;
    const uint32_t aAddr = (uint32_t)((wm * 64 + ((lane >> 3) & 1) * 8 + lane8) * 144
                                      + (lane >> 4) * 16);
    const uint32_t bAddr = (uint32_t)(18432 + (wn * 32 + (lane >> 4) * 8 + lane8) * 144
                                      + ((lane >> 3) & 1) * 16);

    int str = 2;                 // stage to write next
    int srd = 0;                 // stage to read
    for (int c = 0; c < GKC64; c++) {
        WAITG1();
        __syncthreads();
        if (c + 2 < GKC64) ISSUE(c + 2, str);
        COMMIT();
        if (++str == 3) str = 0;

        const uint32_t st = sbase + (uint32_t)srd * GSTAGE_BYTES;
        if (++srd == 3) srd = 0;
#pragma unroll
        for (int ks = 0; ks < 4; ks++) {
            uint32_t a[4][4], b[2][4];
#pragma unroll
            for (int i = 0; i < 4; i++)
                ldsm_x4(a[i], st + aAddr + i * (16 * 144) + ks * 32);
#pragma unroll
            for (int jp = 0; jp < 2; jp++)
                ldsm_x4(b[jp], st + bAddr + jp * (16 * 144) + ks * 32);
#pragma unroll
            for (int i = 0; i < 4; i++)
#pragma unroll
                for (int j = 0; j < 4; j++)
                    mma_bf16(acc[i][j], a[i], &b[j >> 1][(j & 1) * 2]);
        }
    }

#pragma unroll
    for (int i = 0; i < 4; i++) {
        int m0 = mbase + wm * 64 + i * 16 + (lane >> 2);
#pragma unroll
        for (int j = 0; j < 4; j++) {
            int n0 = nbase + wn * 32 + j * 8 + (lane & 3) * 2;
            if constexpr (MODE == 0) {
                *(float2*)(C + (size_t)m0 * Ncols + n0) =
                    make_float2(acc[i][j][0], acc[i][j][1]);
                *(float2*)(C + (size_t)(m0 + 8) * Ncols + n0) =
                    make_float2(acc[i][j][2], acc[i][j][3]);
            } else {
                int mp = n0 / 768;
                int rr = n0 - mp * 768;
                int which = rr >> 8;
                int ccc = rr & 255;
                int hh = mp * 2 + (ccc >> 7);
                int dd = ccc & 127;
                int bb = m0 >> 11, ss = m0 & 2047;
                int bh2 = bb * Hh + hh;
                float v0 = acc[i][j][0], v1 = acc[i][j][1];
                float v2 = acc[i][j][2], v3 = acc[i][j][3];
                if (which == 2) {
                    size_t vb = ((size_t)bh2 * 2 * Dh + dd) * (size_t)Ss + ss;
                    const size_t PL = (size_t)Dh * Ss;
                    __half a0 = __float2half(v0);
                    g_vt[vb] = a0;
                    g_vt[vb + PL] = __float2half(v0 - __half2float(a0));
                    __half a1 = __float2half(v1);
                    g_vt[vb + Ss] = a1;
                    g_vt[vb + Ss + PL] = __float2half(v1 - __half2float(a1));
                    __half a2 = __float2half(v2);
                    g_vt[vb + 8] = a2;
                    g_vt[vb + 8 + PL] = __float2half(v2 - __half2float(a2));
                    __half a3 = __float2half(v3);
                    g_vt[vb + Ss + 8] = a3;
                    g_vt[vb + Ss + 8 + PL] = __float2half(v3 - __half2float(a3));
                } else {
                    if (dd < 32) {
                        int ir = dd >> 1;
                        float2 cs1 = *(float2*)&g_rope[((size_t)ss * 16 + ir) * 2];
                        float2 cs2 = *(float2*)&g_rope[((size_t)(ss + 8) * 16 + ir) * 2];
                        float t0 = v0 * cs1.x - v1 * cs1.y;
                        v1 = v1 * cs1.x + v0 * cs1.y; v0 = t0;
                        t0 = v2 * cs2.x - v3 * cs2.y;
                        v3 = v3 * cs2.x + v2 * cs2.y; v2 = t0;
                    }
                    if (which == 0) {
                        const float sc = 0.08838834764831845f;
                        v0 *= sc; v1 *= sc; v2 *= sc; v3 *= sc;
                    }
                    __half* P = (which == 0) ? g_qp : g_kp;
                    size_t rb = ((size_t)bh2 * Ss + ss) * 256 + dd;
                    __half h0 = __float2half(v0), h1 = __float2half(v1);
                    __half h2 = __float2half(v2), h3 = __float2half(v3);
                    __half l0 = __float2half(v0 - __half2float(h0));
                    __half l1 = __float2half(v1 - __half2float(h1));
                    __half l2 = __float2half(v2 - __half2float(h2));
                    __half l3 = __float2half(v3 - __half2float(h3));
                    *(__half2*)(P + rb) = __halves2half2(h0, h1);
                    *(__half2*)(P + rb + 128) = __halves2half2(l0, l1);
                    *(__half2*)(P + rb + 8 * 256) = __halves2half2(h2, h3);
                    *(__half2*)(P + rb + 8 * 256 + 128) = __halves2half2(l2, l3);
                }
            }
        }
    }
}

// ---------------------------------------------------------------------------
// Tensor-core flash attention (unchanged from R6).
// ---------------------------------------------------------------------------
#define ATTN3_SMEM 154624

__global__ __launch_bounds__(256, 1) void attn3(
    const __half* __restrict__ qp, const __half* __restrict__ kp,
    const __half* __restrict__ vt)
{
    extern __shared__ char sm3[];
    const uint32_t sb = smem_u32(sm3);
    const uint32_t Qs = sb;
    const uint32_t Ks = sb + 67584;
    const uint32_t Vs = sb + 101376;
    const uint32_t Ps = sb + 136192;
    char* PsC = sm3 + 136192;

    const int qb = (int)gridDim.x - 1 - (int)blockIdx.x;
    const int h = blockIdx.y, b = blockIdx.z;
    const int bh = b * Hh + h;
    const int tid = threadIdx.x, lane = tid & 31, w = tid >> 5;
    const int qbase = qb * 128;

    {
        const __half* qg = qp + ((size_t)bh * Ss + qbase) * 256;
#pragma unroll
        for (int t = 0; t < 16; t++) {
            int u = tid + t * 256;
            int r = u >> 5, sg = u & 31;
            uint32_t dst = Qs + r * 528 + sg * 16;
            asm volatile("cp.async.cg.shared.global [%0], [%1], 16;"
                         :: "r"(dst), "l"(qg + r * 256 + sg * 8));
        }
        asm volatile("cp.async.commit_group;" ::: "memory");
    }

    float O[16][4];
#pragma unroll
    for (int i = 0; i < 16; i++)
#pragma unroll
        for (int r = 0; r < 4; r++) O[i][r] = 0.f;
    float m[2] = {-1e30f, -1e30f}, l[2] = {0.f, 0.f};

    const uint32_t aQ = Qs + (w * 16 + (lane & 15)) * 528 + (lane >> 4) * 16;
    const uint32_t bK = Ks + ((lane >> 4) * 8 + (lane & 7)) * 528 + ((lane >> 3) & 1) * 16;
    const uint32_t aP = Ps + (w * 16 + (lane & 15)) * 144 + (lane >> 4) * 16;
    const uint32_t bV = Vs + ((lane >> 4) * 8 + (lane & 7)) * 272 + ((lane >> 3) & 1) * 16;

    const int ntiles = 2 * qb + 2;
    for (int t = 0; t < ntiles; t++) {
        const int j0 = t * 64;
        __syncthreads();
        {
            const __half* kg = kp + ((size_t)bh * Ss + j0) * 256;
#pragma unroll
            for (int tt = 0; tt < 8; tt++) {
                int u = tid + tt * 256;
                int r = u >> 5, sg = u & 31;
                uint32_t dst = Ks + r * 528 + sg * 16;
                asm volatile("cp.async.cg.shared.global [%0], [%1], 16;"
                             :: "r"(dst), "l"(kg + r * 256 + sg * 8));
            }
        }
        {
            const __half* vg = vt + (size_t)bh * 2 * Dh * Ss + j0;
#pragma unroll
            for (int tt = 0; tt < 8; tt++) {
                int u = tid + tt * 256;
                int pd = u >> 3, sg = u & 7;
                int pl = pd >> 7, d = pd & 127;
                uint32_t dst = Vs + d * 272 + pl * 128 + sg * 16;
                asm volatile("cp.async.cg.shared.global [%0], [%1], 16;"
                             :: "r"(dst), "l"(vg + (size_t)pd * Ss + sg * 8));
            }
        }
        asm volatile("cp.async.commit_group;" ::: "memory");
        asm volatile("cp.async.wait_group 0;" ::: "memory");
        __syncthreads();

        float s[8][4];
#pragma unroll
        for (int nt = 0; nt < 8; nt++)
#pragma unroll
            for (int r = 0; r < 4; r++) s[nt][r] = 0.f;
#pragma unroll
        for (int pass = 0; pass < 3; pass++) {
            const uint32_t ao = (pass == 2) ? 256u : 0u;
            const uint32_t bo = (pass == 1) ? 256u : 0u;
#pragma unroll
            for (int c = 0; c < 8; c++) {
                uint32_t a[4];
                ldsm_x4(a, aQ + ao + c * 32);
#pragma unroll
                for (int np = 0; np < 4; np++) {
                    uint32_t bf[4];
                    ldsm_x4(bf, bK + bo + c * 32 + np * (16 * 528));
                    mma_fp16(s[np * 2 + 0], a, &bf[0]);
                    mma_fp16(s[np * 2 + 1], a, &bf[2]);
                }
            }
        }

        if (t >= ntiles - 2) {
#pragma unroll
            for (int nt = 0; nt < 8; nt++)
#pragma unroll
                for (int r = 0; r < 4; r++) {
                    int grow2 = qbase + w * 16 + (lane >> 2) + (r >> 1) * 8;
                    int gcol = j0 + nt * 8 + (lane & 3) * 2 + (r & 1);
                    if (gcol > grow2) s[nt][r] = -1e9f;
                }
        }

        float corr[2];
#pragma unroll
        for (int hh = 0; hh < 2; hh++) {
            float cm = -1e30f;
#pragma unroll
            for (int nt = 0; nt < 8; nt++)
                cm = fmaxf(cm, fmaxf(s[nt][hh * 2], s[nt][hh * 2 + 1]));
            cm = fmaxf(cm, __shfl_xor_sync(0xffffffffu, cm, 1));
            cm = fmaxf(cm, __shfl_xor_sync(0xffffffffu, cm, 2));
            float mn = fmaxf(m[hh], cm);
            corr[hh] = __expf(m[hh] - mn);
            m[hh] = mn;
            float ps = 0.f;
            int prow = w * 16 + (lane >> 2) + hh * 8;
#pragma unroll
            for (int nt = 0; nt < 8; nt++) {
                float p0 = __expf(s[nt][hh * 2] - mn);
                float p1 = __expf(s[nt][hh * 2 + 1] - mn);
                ps += p0 + p1;
                *(__half2*)(PsC + prow * 144 + (nt * 8 + (lane & 3) * 2) * 2) =
                    __floats2half2_rn(p0, p1);
            }
            ps += __shfl_xor_sync(0xffffffffu, ps, 1);
            ps += __shfl_xor_sync(0xffffffffu, ps, 2);
            l[hh] = l[hh] * corr[hh] + ps;
        }
#pragma unroll
        for (int i = 0; i < 16; i++) {
            O[i][0] *= corr[0]; O[i][1] *= corr[0];
            O[i][2] *= corr[1]; O[i][3] *= corr[1];
        }
        __syncthreads();

#pragma unroll
        for (int c = 0; c < 4; c++) {
            uint32_t a[4];
            ldsm_x4(a, aP + c * 32);
#pragma unroll
            for (int pass = 0; pass < 2; pass++) {
                const uint32_t bo = pass * 128u;
#pragma unroll
                for (int np = 0; np < 8; np++) {
                    uint32_t bf[4];
                    ldsm_x4(bf, bV + bo + c * 32 + np * (16 * 272));
                    mma_fp16(O[np * 2 + 0], a, &bf[0]);
                    mma_fp16(O[np * 2 + 1], a, &bf[2]);
                }
            }
        }
    }

    float inv0 = 1.f / l[0], inv1 = 1.f / l[1];
#pragma unroll
    for (int nt = 0; nt < 16; nt++) {
        int col = h * 128 + nt * 8 + (lane & 3) * 2;
#pragma unroll
        for (int hh = 0; hh < 2; hh++) {
            float inv = hh ? inv1 : inv0;
            float o0 = O[nt][hh * 2] * inv;
            float o1 = O[nt][hh * 2 + 1] * inv;
            int srow = qbase + w * 16 + (lane >> 2) + hh * 8;
            size_t rb = ((size_t)(b * Ss + srow)) * GK + col;
            __nv_bfloat16 h0, l0b, h1, l1b;
            split_bf16(o0, h0, l0b);
            split_bf16(o1, h1, l1b);
            __nv_bfloat162 hp = {h0, h1}, lp = {l0b, l1b};
            *(__nv_bfloat162*)(g_a_p + rb) = hp;
            *(__nv_bfloat162*)(g_a_p + rb + 2048) = hp;
            *(__nv_bfloat162*)(g_a_p + rb + 4096) = lp;
        }
    }
}

// ---------------------------------------------------------------------------
extern "C" void kernel_launch(void* const* d_in, const int* in_sizes, int n_in,
                              void* d_out, int out_size)
{
    const float* hidden = (const float*)d_in[0];
    const float* wqkv   = (const float*)d_in[1];
    const float* wout   = (const float*)d_in[2];
    float* out = (float*)d_out;

    __nv_bfloat16 *pap, *pwqkv, *pwout;
    __half *pqp, *pkp, *pvt;
    cudaGetSymbolAddress((void**)&pap,   g_a_p);
    cudaGetSymbolAddress((void**)&pwqkv, g_wqkv_p);
    cudaGetSymbolAddress((void**)&pwout, g_wout_p);
    cudaGetSymbolAddress((void**)&pqp,   g_qp);
    cudaGetSymbolAddress((void**)&pkp,   g_kp);
    cudaGetSymbolAddress((void**)&pvt,   g_vt);

    cudaFuncSetAttribute(gemm_mma<0>, cudaFuncAttributeMaxDynamicSharedMemorySize,
                         GEMM_SMEM_BYTES);
    cudaFuncSetAttribute(gemm_mma<1>, cudaFuncAttributeMaxDynamicSharedMemorySize,
                         GEMM_SMEM_BYTES);
    cudaFuncSetAttribute(attn3, cudaFuncAttributeMaxDynamicSharedMemorySize,
                         ATTN3_SMEM);

    // Rope table + packs (weights, activations)
    rope_init<<<(Ss * 16) / 256, 256>>>();
    {
        int t4 = (3 * Ee * Ee) / 4;
        pack_kernel<0><<<(t4 + 255) / 256, 256>>>(wqkv, pwqkv, t4);
        t4 = (Ee * Ee) / 4;
        pack_kernel<0><<<(t4 + 255) / 256, 256>>>(wout, pwout, t4);
        t4 = (Bb * Ss * Ee) / 4;
        pack_kernel<1><<<(t4 + 255) / 256, 256>>>(hidden, pap, t4);
    }
    // 1) QKV projection + fused rope/scale/fp16-pack epilogue
    {
        dim3 grid(3 * Ee / 128, Bb * Ss / 128);  // (48, 32)
        gemm_mma<1><<<grid, 256, GEMM_SMEM_BYTES>>>(pap, pwqkv, nullptr, 0);
    }
    // 2) Tensor-core flash attention -> bf16 A-pack in g_a_p
    {
        dim3 grid(Ss / 128, Hh, Bb);  // (16,16,2)
        attn3<<<grid, 256, ATTN3_SMEM>>>(pqp, pkp, pvt);
    }
    // 3) Output projection
    {
        dim3 grid(Ee / 128, Bb * Ss / 128);  // (16, 32)
        gemm_mma<0><<<grid, 256, GEMM_SMEM_BYTES>>>(pap, pwout, out, Ee);
    }
}

// round 9
// speedup vs baseline: 3.3865x; 2.7052x over previous
#include <cuda_runtime.h>
#include <cuda_bf16.h>
#include <cuda_fp16.h>
#include <math.h>
#include <cstdint>

#define Bb 2
#define Ss 2048
#define Ee 2048
#define Hh 16
#define Dh 128
#define GK 2048          // fp16 single-pass: K = E
#define GKC64 32         // GK / 64 chunks

#define GSTAGE_BYTES 36864                      // (A 128 + B 128 rows) * 144 B
#define GEMM_SMEM_BYTES (3 * GSTAGE_BYTES)      // 110592 -> 2 CTAs/SM

// ---------------- scratch (__device__ globals; no allocation allowed) -------
__device__ __half g_a_p[(size_t)Bb * Ss * GK];        // fp16 activations
__device__ __half g_wqkv_p[(size_t)3 * Ee * GK];      // fp16 Wqkv
__device__ __half g_wout_p[(size_t)Ee * GK];          // fp16 Wout
__device__ __half g_qp[(size_t)Bb * Hh * Ss * Dh];    // q fp16, roped+scaled
__device__ __half g_kp[(size_t)Bb * Hh * Ss * Dh];    // k fp16, roped
__device__ __half g_vt[(size_t)Bb * Hh * Dh * Ss];    // V^T fp16
__device__ float g_rope[(size_t)Ss * 16 * 2];         // (cos,sin) per (s, i)

__device__ __forceinline__ uint32_t smem_u32(const void* p) {
    uint32_t a;
    asm("{ .reg .u64 t; cvta.to.shared.u64 t, %1; cvt.u32.u64 %0, t; }"
        : "=r"(a) : "l"(p));
    return a;
}

// ---------------------------------------------------------------------------
__global__ void rope_init()
{
    int idx = blockIdx.x * blockDim.x + threadIdx.x;   // Ss*16
    int i = idx & 15, s = idx >> 4;
    float f = powf(10000.f, -(float)i * 0.0625f);
    float sn, cs;
    sincosf((float)s * f, &sn, &cs);
    *(float2*)&g_rope[(size_t)idx * 2] = make_float2(cs, sn);
}

// ---------------------------------------------------------------------------
// Pack: fp32 -> fp16 (rows of 2048)
// ---------------------------------------------------------------------------
__global__ __launch_bounds__(256) void pack_fp16(
    const float* __restrict__ src, __half* __restrict__ dst, int total4)
{
    int i = blockIdx.x * blockDim.x + threadIdx.x;
    if (i >= total4) return;
    float4 x = *(const float4*)(src + (size_t)i * 4);
    __half2 p0 = __floats2half2_rn(x.x, x.y);
    __half2 p1 = __floats2half2_rn(x.z, x.w);
    *(__half2*)(dst + (size_t)i * 4) = p0;
    *(__half2*)(dst + (size_t)i * 4 + 2) = p1;
}

// ---------------------------------------------------------------------------
// mma helpers
// ---------------------------------------------------------------------------
__device__ __forceinline__ void mma_fp16(float* c, const uint32_t* a, const uint32_t* b) {
    asm volatile(
        "mma.sync.aligned.m16n8k16.row.col.f32.f16.f16.f32 "
        "{%0,%1,%2,%3}, {%4,%5,%6,%7}, {%8,%9}, {%0,%1,%2,%3};"
        : "+f"(c[0]), "+f"(c[1]), "+f"(c[2]), "+f"(c[3])
        : "r"(a[0]), "r"(a[1]), "r"(a[2]), "r"(a[3]), "r"(b[0]), "r"(b[1]));
}
__device__ __forceinline__ void ldsm_x4(uint32_t* r, uint32_t addr) {
    asm volatile("ldmatrix.sync.aligned.m8n8.x4.shared.b16 {%0,%1,%2,%3}, [%4];"
        : "=r"(r[0]), "=r"(r[1]), "=r"(r[2]), "=r"(r[3]) : "r"(addr));
}

// ---------------------------------------------------------------------------
// fp16 GEMM: C[M,N] = A[M,2048] * B[N,2048]^T.  CTA 128x128, 8 warps
// (2M x 4N), warp tile 64x32.  K-chunk 64, 3-stage cp.async, 144 B pitch.
// MODE 0: fp32 store.  MODE 1: QKV epilogue (rope table + fp16 q/k/v^T).
// ---------------------------------------------------------------------------
template <int MODE>
__global__ __launch_bounds__(256, 2) void gemm_mma(
    const __half* __restrict__ A, const __half* __restrict__ Bw,
    float* __restrict__ C, int Ncols)
{
    extern __shared__ __align__(16) uint32_t gsm[];
    const uint32_t sbase = smem_u32(gsm);

    const int tid = threadIdx.x;
    const int lane = tid & 31, w = tid >> 5;
    const int wm = w & 1, wn = w >> 1;
    const int mbase = blockIdx.y * 128, nbase = blockIdx.x * 128;

    float acc[4][4][4];
#pragma unroll
    for (int i = 0; i < 4; i++)
#pragma unroll
        for (int j = 0; j < 4; j++)
#pragma unroll
            for (int r = 0; r < 4; r++) acc[i][j][r] = 0.f;

    const int grow = tid >> 3, gseg = tid & 7;
    const __half* Ag = A + (size_t)(mbase + grow) * GK + gseg * 8;
    const __half* Bg = Bw + (size_t)(nbase + grow) * GK + gseg * 8;
    const size_t rstep32 = (size_t)32 * GK;
    const uint32_t dbase = grow * 144 + gseg * 16;

#define ISSUE(c, str) do {                                                     \
    uint32_t st = sbase + (uint32_t)(str) * GSTAGE_BYTES;                      \
    const __half* sA = Ag + (size_t)(c) * 64;                                  \
    const __half* sB = Bg + (size_t)(c) * 64;                                  \
    _Pragma("unroll")                                                          \
    for (int j = 0; j < 4; j++) {                                              \
        asm volatile("cp.async.cg.shared.global [%0], [%1], 16;"               \
            :: "r"(st + dbase + j * (32 * 144)), "l"(sA + j * rstep32));       \
        asm volatile("cp.async.cg.shared.global [%0], [%1], 16;"               \
            :: "r"(st + 18432 + dbase + j * (32 * 144)), "l"(sB + j * rstep32)); \
    }                                                                          \
} while (0)
#define COMMIT() asm volatile("cp.async.commit_group;" ::: "memory")
#define WAITG1() asm volatile("cp.async.wait_group 1;" ::: "memory")

    ISSUE(0, 0); COMMIT();
    ISSUE(1, 1); COMMIT();

    const int lane8 = lane & 7;
    const uint32_t aAddr = (uint32_t)((wm * 64 + ((lane >> 3) & 1) * 8 + lane8) * 144
                                      + (lane >> 4) * 16);
    const uint32_t bAddr = (uint32_t)(18432 + (wn * 32 + (lane >> 4) * 8 + lane8) * 144
                                      + ((lane >> 3) & 1) * 16);

    int str = 2, srd = 0;
    for (int c = 0; c < GKC64; c++) {
        WAITG1();
        __syncthreads();
        if (c + 2 < GKC64) ISSUE(c + 2, str);
        COMMIT();
        if (++str == 3) str = 0;

        const uint32_t st = sbase + (uint32_t)srd * GSTAGE_BYTES;
        if (++srd == 3) srd = 0;
#pragma unroll
        for (int ks = 0; ks < 4; ks++) {
            uint32_t a[4][4], b[2][4];
#pragma unroll
            for (int i = 0; i < 4; i++)
                ldsm_x4(a[i], st + aAddr + i * (16 * 144) + ks * 32);
#pragma unroll
            for (int jp = 0; jp < 2; jp++)
                ldsm_x4(b[jp], st + bAddr + jp * (16 * 144) + ks * 32);
#pragma unroll
            for (int i = 0; i < 4; i++)
#pragma unroll
                for (int j = 0; j < 4; j++)
                    mma_fp16(acc[i][j], a[i], &b[j >> 1][(j & 1) * 2]);
        }
    }

#pragma unroll
    for (int i = 0; i < 4; i++) {
        int m0 = mbase + wm * 64 + i * 16 + (lane >> 2);
#pragma unroll
        for (int j = 0; j < 4; j++) {
            int n0 = nbase + wn * 32 + j * 8 + (lane & 3) * 2;
            if constexpr (MODE == 0) {
                *(float2*)(C + (size_t)m0 * Ncols + n0) =
                    make_float2(acc[i][j][0], acc[i][j][1]);
                *(float2*)(C + (size_t)(m0 + 8) * Ncols + n0) =
                    make_float2(acc[i][j][2], acc[i][j][3]);
            } else {
                int mp = n0 / 768;
                int rr = n0 - mp * 768;
                int which = rr >> 8;
                int ccc = rr & 255;
                int hh = mp * 2 + (ccc >> 7);
                int dd = ccc & 127;
                int bb = m0 >> 11, ss = m0 & 2047;
                int bh2 = bb * Hh + hh;
                float v0 = acc[i][j][0], v1 = acc[i][j][1];
                float v2 = acc[i][j][2], v3 = acc[i][j][3];
                if (which == 2) {
                    // V^T single fp16 plane: [bh, d, s]
                    size_t vb = ((size_t)bh2 * Dh + dd) * (size_t)Ss + ss;
                    g_vt[vb] = __float2half(v0);
                    g_vt[vb + Ss] = __float2half(v1);
                    g_vt[vb + 8] = __float2half(v2);
                    g_vt[vb + Ss + 8] = __float2half(v3);
                } else {
                    if (dd < 32) {
                        int ir = dd >> 1;
                        float2 cs1 = *(float2*)&g_rope[((size_t)ss * 16 + ir) * 2];
                        float2 cs2 = *(float2*)&g_rope[((size_t)(ss + 8) * 16 + ir) * 2];
                        float t0 = v0 * cs1.x - v1 * cs1.y;
                        v1 = v1 * cs1.x + v0 * cs1.y; v0 = t0;
                        t0 = v2 * cs2.x - v3 * cs2.y;
                        v3 = v3 * cs2.x + v2 * cs2.y; v2 = t0;
                    }
                    if (which == 0) {
                        const float sc = 0.08838834764831845f;
                        v0 *= sc; v1 *= sc; v2 *= sc; v3 *= sc;
                    }
                    __half* P = (which == 0) ? g_qp : g_kp;
                    size_t rb = ((size_t)bh2 * Ss + ss) * Dh + dd;
                    *(__half2*)(P + rb) = __floats2half2_rn(v0, v1);
                    *(__half2*)(P + rb + 8 * Dh) = __floats2half2_rn(v2, v3);
                }
            }
        }
    }
}

// ---------------------------------------------------------------------------
// Flash attention v4: single-pass fp16 QK and PV, double-buffered K/V tiles.
// CTA = 128 q rows, 8 warps (16 q rows each), KV tile 64.
// smem: Qs 128x272 + 2x(Ks 64x272) + 2x(Vs 128x144) + Ps 128x144 = 124928 B.
// Epilogue writes fp16 activations [B,S,E] into g_a_p for the out-proj.
// ---------------------------------------------------------------------------
#define ATTN_SMEM 124928

__global__ __launch_bounds__(256, 1) void attn4(
    const __half* __restrict__ qp, const __half* __restrict__ kp,
    const __half* __restrict__ vt)
{
    extern __shared__ char sm4[];
    const uint32_t sb = smem_u32(sm4);
    const uint32_t Qs = sb;
    const uint32_t Ks0 = sb + 34816;     // + buf*17408
    const uint32_t Vs0 = sb + 69632;     // + buf*18432
    const uint32_t Ps = sb + 106496;
    char* PsC = sm4 + 106496;

    const int qb = (int)gridDim.x - 1 - (int)blockIdx.x;   // long blocks first
    const int h = blockIdx.y, b = blockIdx.z;
    const int bh = b * Hh + h;
    const int tid = threadIdx.x, lane = tid & 31, w = tid >> 5;
    const int qbase = qb * 128;
    const int ntiles = 2 * qb + 2;

    // Q tile: 128 rows x 128 halves
    {
        const __half* qg = qp + ((size_t)bh * Ss + qbase) * Dh;
#pragma unroll
        for (int t = 0; t < 8; t++) {
            int u = tid + t * 256;
            int r = u >> 4, sg = u & 15;
            asm volatile("cp.async.cg.shared.global [%0], [%1], 16;"
                :: "r"(Qs + r * 272 + sg * 16), "l"(qg + r * Dh + sg * 8));
        }
        asm volatile("cp.async.commit_group;" ::: "memory");
    }

#define ISSUE_T(tt, buf) do {                                                  \
    const __half* kg = kp + ((size_t)bh * Ss + (tt) * 64) * Dh;                \
    uint32_t kd = Ks0 + (buf) * 17408;                                         \
    _Pragma("unroll")                                                          \
    for (int t_ = 0; t_ < 4; t_++) {                                           \
        int u = tid + t_ * 256;                                                \
        int r = u >> 4, sg = u & 15;                                           \
        asm volatile("cp.async.cg.shared.global [%0], [%1], 16;"               \
            :: "r"(kd + r * 272 + sg * 16), "l"(kg + r * Dh + sg * 8));        \
    }                                                                          \
    const __half* vg = vt + (size_t)bh * Dh * Ss + (tt) * 64;                  \
    uint32_t vd = Vs0 + (buf) * 18432;                                         \
    _Pragma("unroll")                                                          \
    for (int t_ = 0; t_ < 4; t_++) {                                           \
        int u = tid + t_ * 256;                                                \
        int r = u >> 3, sg = u & 7;                                            \
        asm volatile("cp.async.cg.shared.global [%0], [%1], 16;"               \
            :: "r"(vd + r * 144 + sg * 16), "l"(vg + (size_t)r * Ss + sg * 8)); \
    }                                                                          \
} while (0)

    ISSUE_T(0, 0);
    asm volatile("cp.async.commit_group;" ::: "memory");
    if (ntiles > 1) ISSUE_T(1, 1);
    asm volatile("cp.async.commit_group;" ::: "memory");

    float O[16][4];
#pragma unroll
    for (int i = 0; i < 16; i++)
#pragma unroll
        for (int r = 0; r < 4; r++) O[i][r] = 0.f;
    float m[2] = {-1e30f, -1e30f}, l[2] = {0.f, 0.f};

    const uint32_t aQ = Qs + (w * 16 + (lane & 15)) * 272 + (lane >> 4) * 16;
    const uint32_t aP = Ps + (w * 16 + (lane & 15)) * 144 + (lane >> 4) * 16;
    const int bRow = (lane >> 4) * 8 + (lane & 7);
    const int bCol = ((lane >> 3) & 1) * 16;

    for (int t = 0; t < ntiles; t++) {
        asm volatile("cp.async.wait_group 1;" ::: "memory");
        __syncthreads();
        const int buf = t & 1;
        const uint32_t bK = Ks0 + buf * 17408 + bRow * 272 + bCol;
        const uint32_t bV = Vs0 + buf * 18432 + bRow * 144 + bCol;

        // ---- QK single pass
        float s[8][4];
#pragma unroll
        for (int nt = 0; nt < 8; nt++)
#pragma unroll
            for (int r = 0; r < 4; r++) s[nt][r] = 0.f;
#pragma unroll
        for (int c = 0; c < 8; c++) {
            uint32_t a[4];
            ldsm_x4(a, aQ + c * 32);
#pragma unroll
            for (int np = 0; np < 4; np++) {
                uint32_t bf[4];
                ldsm_x4(bf, bK + c * 32 + np * (16 * 272));
                mma_fp16(s[np * 2 + 0], a, &bf[0]);
                mma_fp16(s[np * 2 + 1], a, &bf[2]);
            }
        }

        // ---- causal mask (last two tiles)
        if (t >= ntiles - 2) {
            const int j0 = t * 64;
#pragma unroll
            for (int nt = 0; nt < 8; nt++)
#pragma unroll
                for (int r = 0; r < 4; r++) {
                    int grow2 = qbase + w * 16 + (lane >> 2) + (r >> 1) * 8;
                    int gcol = j0 + nt * 8 + (lane & 3) * 2 + (r & 1);
                    if (gcol > grow2) s[nt][r] = -1e9f;
                }
        }

        // ---- online softmax (rows are warp-private; no barrier needed)
        float corr[2];
#pragma unroll
        for (int hh = 0; hh < 2; hh++) {
            float cm = -1e30f;
#pragma unroll
            for (int nt = 0; nt < 8; nt++)
                cm = fmaxf(cm, fmaxf(s[nt][hh * 2], s[nt][hh * 2 + 1]));
            cm = fmaxf(cm, __shfl_xor_sync(0xffffffffu, cm, 1));
            cm = fmaxf(cm, __shfl_xor_sync(0xffffffffu, cm, 2));
            float mn = fmaxf(m[hh], cm);
            corr[hh] = __expf(m[hh] - mn);
            m[hh] = mn;
            float ps = 0.f;
            int prow = w * 16 + (lane >> 2) + hh * 8;
#pragma unroll
            for (int nt = 0; nt < 8; nt++) {
                float p0 = __expf(s[nt][hh * 2] - mn);
                float p1 = __expf(s[nt][hh * 2 + 1] - mn);
                ps += p0 + p1;
                *(__half2*)(PsC + prow * 144 + (nt * 8 + (lane & 3) * 2) * 2) =
                    __floats2half2_rn(p0, p1);
            }
            ps += __shfl_xor_sync(0xffffffffu, ps, 1);
            ps += __shfl_xor_sync(0xffffffffu, ps, 2);
            l[hh] = l[hh] * corr[hh] + ps;
        }
#pragma unroll
        for (int i = 0; i < 16; i++) {
            O[i][0] *= corr[0]; O[i][1] *= corr[0];
            O[i][2] *= corr[1]; O[i][3] *= corr[1];
        }

        // ---- PV single pass
#pragma unroll
        for (int c = 0; c < 4; c++) {
            uint32_t a[4];
            ldsm_x4(a, aP + c * 32);
#pragma unroll
            for (int np = 0; np < 8; np++) {
                uint32_t bf[4];
                ldsm_x4(bf, bV + c * 32 + np * (16 * 144));
                mma_fp16(O[np * 2 + 0], a, &bf[0]);
                mma_fp16(O[np * 2 + 1], a, &bf[2]);
            }
        }

        __syncthreads();   // all warps done reading buf before overwrite
        if (t + 2 < ntiles) ISSUE_T(t + 2, buf);
        asm volatile("cp.async.commit_group;" ::: "memory");
    }

    // ---- epilogue: normalize, write fp16 activations [B,S,E]
    float inv0 = 1.f / l[0], inv1 = 1.f / l[1];
#pragma unroll
    for (int nt = 0; nt < 16; nt++) {
        int col = h * 128 + nt * 8 + (lane & 3) * 2;
#pragma unroll
        for (int hh = 0; hh < 2; hh++) {
            float inv = hh ? inv1 : inv0;
            int srow = qbase + w * 16 + (lane >> 2) + hh * 8;
            size_t rb = ((size_t)(b * Ss + srow)) * GK + col;
            *(__half2*)(g_a_p + rb) =
                __floats2half2_rn(O[nt][hh * 2] * inv, O[nt][hh * 2 + 1] * inv);
        }
    }
}

// ---------------------------------------------------------------------------
extern "C" void kernel_launch(void* const* d_in, const int* in_sizes, int n_in,
                              void* d_out, int out_size)
{
    const float* hidden = (const float*)d_in[0];
    const float* wqkv   = (const float*)d_in[1];
    const float* wout   = (const float*)d_in[2];
    float* out = (float*)d_out;

    __half *pap, *pwqkv, *pwout, *pqp, *pkp, *pvt;
    cudaGetSymbolAddress((void**)&pap,   g_a_p);
    cudaGetSymbolAddress((void**)&pwqkv, g_wqkv_p);
    cudaGetSymbolAddress((void**)&pwout, g_wout_p);
    cudaGetSymbolAddress((void**)&pqp,   g_qp);
    cudaGetSymbolAddress((void**)&pkp,   g_kp);
    cudaGetSymbolAddress((void**)&pvt,   g_vt);

    cudaFuncSetAttribute(gemm_mma<0>, cudaFuncAttributeMaxDynamicSharedMemorySize,
                         GEMM_SMEM_BYTES);
    cudaFuncSetAttribute(gemm_mma<1>, cudaFuncAttributeMaxDynamicSharedMemorySize,
                         GEMM_SMEM_BYTES);
    cudaFuncSetAttribute(attn4, cudaFuncAttributeMaxDynamicSharedMemorySize,
                         ATTN_SMEM);

    // Rope table + fp16 packs
    rope_init<<<(Ss * 16) / 256, 256>>>();
    {
        int t4 = (3 * Ee * Ee) / 4;
        pack_fp16<<<(t4 + 255) / 256, 256>>>(wqkv, pwqkv, t4);
        t4 = (Ee * Ee) / 4;
        pack_fp16<<<(t4 + 255) / 256, 256>>>(wout, pwout, t4);
        t4 = (Bb * Ss * Ee) / 4;
        pack_fp16<<<(t4 + 255) / 256, 256>>>(hidden, pap, t4);
    }
    // 1) QKV projection + fused rope/scale/fp16 q,k,v^T epilogue
    {
        dim3 grid(3 * Ee / 128, Bb * Ss / 128);  // (48, 32)
        gemm_mma<1><<<grid, 256, GEMM_SMEM_BYTES>>>(pap, pwqkv, nullptr, 0);
    }
    // 2) Flash attention (fp16 single-pass QK/PV) -> fp16 A in g_a_p
    {
        dim3 grid(Ss / 128, Hh, Bb);  // (16,16,2)
        attn4<<<grid, 256, ATTN_SMEM>>>(pqp, pkp, pvt);
    }
    // 3) Output projection
    {
        dim3 grid(Ee / 128, Bb * Ss / 128);  // (16, 32)
        gemm_mma<0><<<grid, 256, GEMM_SMEM_BYTES>>>(pap, pwout, out, Ee);
    }
}

// round 10
// speedup vs baseline: 3.5101x; 1.0365x over previous
#include <cuda_runtime.h>
#include <cuda_bf16.h>
#include <cuda_fp16.h>
#include <math.h>
#include <cstdint>

#define Bb 2
#define Ss 2048
#define Ee 2048
#define Hh 16
#define Dh 128
#define GK 2048          // fp16 single-pass: K = E
#define GKC64 32         // GK / 64 chunks

#define GSTAGE_BYTES 36864                      // (A 128 + B 128 rows) * 144 B
#define GEMM_SMEM_BYTES (3 * GSTAGE_BYTES)      // 110592 -> 2 CTAs/SM

// ---------------- scratch (__device__ globals; no allocation allowed) -------
__device__ __half g_a_p[(size_t)Bb * Ss * GK];        // fp16 activations
__device__ __half g_wqkv_p[(size_t)3 * Ee * GK];      // fp16 Wqkv
__device__ __half g_wout_p[(size_t)Ee * GK];          // fp16 Wout
__device__ __half g_qp[(size_t)Bb * Hh * Ss * Dh];    // q fp16, roped+scaled
__device__ __half g_kp[(size_t)Bb * Hh * Ss * Dh];    // k fp16, roped
__device__ __half g_vt[(size_t)Bb * Hh * Dh * Ss];    // V^T fp16
__device__ float g_rope[(size_t)Ss * 16 * 2];         // (cos,sin) per (s, i)

__device__ __forceinline__ uint32_t smem_u32(const void* p) {
    uint32_t a;
    asm("{ .reg .u64 t; cvta.to.shared.u64 t, %1; cvt.u32.u64 %0, t; }"
        : "=r"(a) : "l"(p));
    return a;
}

// ---------------------------------------------------------------------------
__global__ void rope_init()
{
    int idx = blockIdx.x * blockDim.x + threadIdx.x;   // Ss*16
    int i = idx & 15, s = idx >> 4;
    float f = powf(10000.f, -(float)i * 0.0625f);
    float sn, cs;
    sincosf((float)s * f, &sn, &cs);
    *(float2*)&g_rope[(size_t)idx * 2] = make_float2(cs, sn);
}

// ---------------------------------------------------------------------------
// Pack: fp32 -> fp16, grid-stride x4 for memory-level parallelism.
// ---------------------------------------------------------------------------
__global__ __launch_bounds__(256) void pack_fp16(
    const float* __restrict__ src, __half* __restrict__ dst, int total4)
{
    int i0 = blockIdx.x * (blockDim.x * 4) + threadIdx.x;
#pragma unroll
    for (int t = 0; t < 4; t++) {
        int i = i0 + t * 256;
        if (i < total4) {
            float4 x = *(const float4*)(src + (size_t)i * 4);
            *(__half2*)(dst + (size_t)i * 4) = __floats2half2_rn(x.x, x.y);
            *(__half2*)(dst + (size_t)i * 4 + 2) = __floats2half2_rn(x.z, x.w);
        }
    }
}

// ---------------------------------------------------------------------------
// mma helpers
// ---------------------------------------------------------------------------
__device__ __forceinline__ void mma_fp16(float* c, const uint32_t* a, const uint32_t* b) {
    asm volatile(
        "mma.sync.aligned.m16n8k16.row.col.f32.f16.f16.f32 "
        "{%0,%1,%2,%3}, {%4,%5,%6,%7}, {%8,%9}, {%0,%1,%2,%3};"
        : "+f"(c[0]), "+f"(c[1]), "+f"(c[2]), "+f"(c[3])
        : "r"(a[0]), "r"(a[1]), "r"(a[2]), "r"(a[3]), "r"(b[0]), "r"(b[1]));
}
__device__ __forceinline__ void ldsm_x4(uint32_t* r, uint32_t addr) {
    asm volatile("ldmatrix.sync.aligned.m8n8.x4.shared.b16 {%0,%1,%2,%3}, [%4];"
        : "=r"(r[0]), "=r"(r[1]), "=r"(r[2]), "=r"(r[3]) : "r"(addr));
}

// ---------------------------------------------------------------------------
// fp16 GEMM: C[M,N] = A[M,2048] * B[N,2048]^T.  CTA 128x128, 8 warps
// (2M x 4N), warp tile 64x32.  K-chunk 64, 3-stage cp.async, 144 B pitch.
// MODE 0: fp32 store.  MODE 1: QKV epilogue (rope table + fp16 q/k/v^T).
// ---------------------------------------------------------------------------
template <int MODE>
__global__ __launch_bounds__(256, 2) void gemm_mma(
    const __half* __restrict__ A, const __half* __restrict__ Bw,
    float* __restrict__ C, int Ncols)
{
    extern __shared__ __align__(16) uint32_t gsm[];
    const uint32_t sbase = smem_u32(gsm);

    const int tid = threadIdx.x;
    const int lane = tid & 31, w = tid >> 5;
    const int wm = w & 1, wn = w >> 1;
    const int mbase = blockIdx.y * 128, nbase = blockIdx.x * 128;

    float acc[4][4][4];
#pragma unroll
    for (int i = 0; i < 4; i++)
#pragma unroll
        for (int j = 0; j < 4; j++)
#pragma unroll
            for (int r = 0; r < 4; r++) acc[i][j][r] = 0.f;

    const int grow = tid >> 3, gseg = tid & 7;
    const __half* Ag = A + (size_t)(mbase + grow) * GK + gseg * 8;
    const __half* Bg = Bw + (size_t)(nbase + grow) * GK + gseg * 8;
    const size_t rstep32 = (size_t)32 * GK;
    const uint32_t dbase = grow * 144 + gseg * 16;

#define ISSUE(c, str) do {                                                     \
    uint32_t st = sbase + (uint32_t)(str) * GSTAGE_BYTES;                      \
    const __half* sA = Ag + (size_t)(c) * 64;                                  \
    const __half* sB = Bg + (size_t)(c) * 64;                                  \
    _Pragma("unroll")                                                          \
    for (int j = 0; j < 4; j++) {                                              \
        asm volatile("cp.async.cg.shared.global [%0], [%1], 16;"               \
            :: "r"(st + dbase + j * (32 * 144)), "l"(sA + j * rstep32));       \
        asm volatile("cp.async.cg.shared.global [%0], [%1], 16;"               \
            :: "r"(st + 18432 + dbase + j * (32 * 144)), "l"(sB + j * rstep32)); \
    }                                                                          \
} while (0)
#define COMMIT() asm volatile("cp.async.commit_group;" ::: "memory")
#define WAITG1() asm volatile("cp.async.wait_group 1;" ::: "memory")

    ISSUE(0, 0); COMMIT();
    ISSUE(1, 1); COMMIT();

    const int lane8 = lane & 7;
    const uint32_t aAddr = (uint32_t)((wm * 64 + ((lane >> 3) & 1) * 8 + lane8) * 144
                                      + (lane >> 4) * 16);
    const uint32_t bAddr = (uint32_t)(18432 + (wn * 32 + (lane >> 4) * 8 + lane8) * 144
                                      + ((lane >> 3) & 1) * 16);

    int str = 2, srd = 0;
    for (int c = 0; c < GKC64; c++) {
        WAITG1();
        __syncthreads();
        if (c + 2 < GKC64) ISSUE(c + 2, str);
        COMMIT();
        if (++str == 3) str = 0;

        const uint32_t st = sbase + (uint32_t)srd * GSTAGE_BYTES;
        if (++srd == 3) srd = 0;
#pragma unroll
        for (int ks = 0; ks < 4; ks++) {
            uint32_t a[4][4], b[2][4];
#pragma unroll
            for (int i = 0; i < 4; i++)
                ldsm_x4(a[i], st + aAddr + i * (16 * 144) + ks * 32);
#pragma unroll
            for (int jp = 0; jp < 2; jp++)
                ldsm_x4(b[jp], st + bAddr + jp * (16 * 144) + ks * 32);
#pragma unroll
            for (int i = 0; i < 4; i++)
#pragma unroll
                for (int j = 0; j < 4; j++)
                    mma_fp16(acc[i][j], a[i], &b[j >> 1][(j & 1) * 2]);
        }
    }

#pragma unroll
    for (int i = 0; i < 4; i++) {
        int m0 = mbase + wm * 64 + i * 16 + (lane >> 2);
#pragma unroll
        for (int j = 0; j < 4; j++) {
            int n0 = nbase + wn * 32 + j * 8 + (lane & 3) * 2;
            if constexpr (MODE == 0) {
                *(float2*)(C + (size_t)m0 * Ncols + n0) =
                    make_float2(acc[i][j][0], acc[i][j][1]);
                *(float2*)(C + (size_t)(m0 + 8) * Ncols + n0) =
                    make_float2(acc[i][j][2], acc[i][j][3]);
            } else {
                int mp = n0 / 768;
                int rr = n0 - mp * 768;
                int which = rr >> 8;
                int ccc = rr & 255;
                int hh = mp * 2 + (ccc >> 7);
                int dd = ccc & 127;
                int bb = m0 >> 11, ss = m0 & 2047;
                int bh2 = bb * Hh + hh;
                float v0 = acc[i][j][0], v1 = acc[i][j][1];
                float v2 = acc[i][j][2], v3 = acc[i][j][3];
                if (which == 2) {
                    size_t vb = ((size_t)bh2 * Dh + dd) * (size_t)Ss + ss;
                    g_vt[vb] = __float2half(v0);
                    g_vt[vb + Ss] = __float2half(v1);
                    g_vt[vb + 8] = __float2half(v2);
                    g_vt[vb + Ss + 8] = __float2half(v3);
                } else {
                    if (dd < 32) {
                        int ir = dd >> 1;
                        float2 cs1 = *(float2*)&g_rope[((size_t)ss * 16 + ir) * 2];
                        float2 cs2 = *(float2*)&g_rope[((size_t)(ss + 8) * 16 + ir) * 2];
                        float t0 = v0 * cs1.x - v1 * cs1.y;
                        v1 = v1 * cs1.x + v0 * cs1.y; v0 = t0;
                        t0 = v2 * cs2.x - v3 * cs2.y;
                        v3 = v3 * cs2.x + v2 * cs2.y; v2 = t0;
                    }
                    if (which == 0) {
                        const float sc = 0.08838834764831845f;
                        v0 *= sc; v1 *= sc; v2 *= sc; v3 *= sc;
                    }
                    __half* P = (which == 0) ? g_qp : g_kp;
                    size_t rb = ((size_t)bh2 * Ss + ss) * Dh + dd;
                    *(__half2*)(P + rb) = __floats2half2_rn(v0, v1);
                    *(__half2*)(P + rb + 8 * Dh) = __floats2half2_rn(v2, v3);
                }
            }
        }
    }
}

// ---------------------------------------------------------------------------
// Flash attention v5: Q tile 64 rows, 128 threads (4 warps x 16 rows),
// single-pass fp16 QK/PV, double-buffered K/V (tile 64), 2 CTAs/SM.
// smem: Qs 64x272 + 2x(Ks 64x272) + 2x(Vs 128x144) + Ps 64x144 = 98304 B.
// ---------------------------------------------------------------------------
#define ATTN_SMEM 98304

__global__ __launch_bounds__(128, 2) void attn5(
    const __half* __restrict__ qp, const __half* __restrict__ kp,
    const __half* __restrict__ vt)
{
    extern __shared__ char sm5[];
    const uint32_t sb = smem_u32(sm5);
    const uint32_t Qs = sb;              // 64*272 = 17408
    const uint32_t Ks0 = sb + 17408;     // + buf*17408 (2 bufs)
    const uint32_t Vs0 = sb + 52224;     // + buf*18432 (2 bufs)
    const uint32_t Ps = sb + 89088;      // 64*144 = 9216
    char* PsC = sm5 + 89088;

    const int qb = (int)gridDim.x - 1 - (int)blockIdx.x;   // long blocks first
    const int h = blockIdx.y, b = blockIdx.z;
    const int bh = b * Hh + h;
    const int tid = threadIdx.x, lane = tid & 31, w = tid >> 5;
    const int qbase = qb * 64;
    const int ntiles = qb + 1;

    // Q tile: 64 rows x 128 halves
    {
        const __half* qg = qp + ((size_t)bh * Ss + qbase) * Dh;
#pragma unroll
        for (int t = 0; t < 8; t++) {
            int u = tid + t * 128;
            int r = u >> 4, sg = u & 15;
            asm volatile("cp.async.cg.shared.global [%0], [%1], 16;"
                :: "r"(Qs + r * 272 + sg * 16), "l"(qg + r * Dh + sg * 8));
        }
        asm volatile("cp.async.commit_group;" ::: "memory");
    }

#define ISSUE_T(tt, buf) do {                                                  \
    const __half* kg = kp + ((size_t)bh * Ss + (tt) * 64) * Dh;                \
    uint32_t kd = Ks0 + (buf) * 17408;                                         \
    _Pragma("unroll")                                                          \
    for (int t_ = 0; t_ < 8; t_++) {                                           \
        int u = tid + t_ * 128;                                                \
        int r = u >> 4, sg = u & 15;                                           \
        asm volatile("cp.async.cg.shared.global [%0], [%1], 16;"               \
            :: "r"(kd + r * 272 + sg * 16), "l"(kg + r * Dh + sg * 8));        \
    }                                                                          \
    const __half* vg = vt + (size_t)bh * Dh * Ss + (tt) * 64;                  \
    uint32_t vd = Vs0 + (buf) * 18432;                                         \
    _Pragma("unroll")                                                          \
    for (int t_ = 0; t_ < 8; t_++) {                                           \
        int u = tid + t_ * 128;                                                \
        int r = u >> 3, sg = u & 7;                                            \
        asm volatile("cp.async.cg.shared.global [%0], [%1], 16;"               \
            :: "r"(vd + r * 144 + sg * 16), "l"(vg + (size_t)r * Ss + sg * 8)); \
    }                                                                          \
} while (0)

    ISSUE_T(0, 0);
    asm volatile("cp.async.commit_group;" ::: "memory");
    if (ntiles > 1) ISSUE_T(1, 1);
    asm volatile("cp.async.commit_group;" ::: "memory");

    float O[16][4];
#pragma unroll
    for (int i = 0; i < 16; i++)
#pragma unroll
        for (int r = 0; r < 4; r++) O[i][r] = 0.f;
    float m[2] = {-1e30f, -1e30f}, l[2] = {0.f, 0.f};

    const uint32_t aQ = Qs + (w * 16 + (lane & 15)) * 272 + (lane >> 4) * 16;
    const uint32_t aP = Ps + (w * 16 + (lane & 15)) * 144 + (lane >> 4) * 16;
    const int bRow = (lane >> 4) * 8 + (lane & 7);
    const int bCol = ((lane >> 3) & 1) * 16;

    for (int t = 0; t < ntiles; t++) {
        asm volatile("cp.async.wait_group 1;" ::: "memory");
        __syncthreads();
        const int buf = t & 1;
        const uint32_t bK = Ks0 + buf * 17408 + bRow * 272 + bCol;
        const uint32_t bV = Vs0 + buf * 18432 + bRow * 144 + bCol;

        // ---- QK single pass: 16 q rows x 64 kv cols per warp
        float s[8][4];
#pragma unroll
        for (int nt = 0; nt < 8; nt++)
#pragma unroll
            for (int r = 0; r < 4; r++) s[nt][r] = 0.f;
#pragma unroll
        for (int c = 0; c < 8; c++) {
            uint32_t a[4];
            ldsm_x4(a, aQ + c * 32);
#pragma unroll
            for (int np = 0; np < 4; np++) {
                uint32_t bf[4];
                ldsm_x4(bf, bK + c * 32 + np * (16 * 272));
                mma_fp16(s[np * 2 + 0], a, &bf[0]);
                mma_fp16(s[np * 2 + 1], a, &bf[2]);
            }
        }

        // ---- causal mask (last tile only: j0 = qbase)
        if (t == ntiles - 1) {
            const int j0 = t * 64;
#pragma unroll
            for (int nt = 0; nt < 8; nt++)
#pragma unroll
                for (int r = 0; r < 4; r++) {
                    int grow2 = qbase + w * 16 + (lane >> 2) + (r >> 1) * 8;
                    int gcol = j0 + nt * 8 + (lane & 3) * 2 + (r & 1);
                    if (gcol > grow2) s[nt][r] = -1e9f;
                }
        }

        // ---- online softmax (rows warp-private)
        float corr[2];
#pragma unroll
        for (int hh = 0; hh < 2; hh++) {
            float cm = -1e30f;
#pragma unroll
            for (int nt = 0; nt < 8; nt++)
                cm = fmaxf(cm, fmaxf(s[nt][hh * 2], s[nt][hh * 2 + 1]));
            cm = fmaxf(cm, __shfl_xor_sync(0xffffffffu, cm, 1));
            cm = fmaxf(cm, __shfl_xor_sync(0xffffffffu, cm, 2));
            float mn = fmaxf(m[hh], cm);
            corr[hh] = __expf(m[hh] - mn);
            m[hh] = mn;
            float ps = 0.f;
            int prow = w * 16 + (lane >> 2) + hh * 8;
#pragma unroll
            for (int nt = 0; nt < 8; nt++) {
                float p0 = __expf(s[nt][hh * 2] - mn);
                float p1 = __expf(s[nt][hh * 2 + 1] - mn);
                ps += p0 + p1;
                *(__half2*)(PsC + prow * 144 + (nt * 8 + (lane & 3) * 2) * 2) =
                    __floats2half2_rn(p0, p1);
            }
            ps += __shfl_xor_sync(0xffffffffu, ps, 1);
            ps += __shfl_xor_sync(0xffffffffu, ps, 2);
            l[hh] = l[hh] * corr[hh] + ps;
        }
#pragma unroll
        for (int i = 0; i < 16; i++) {
            O[i][0] *= corr[0]; O[i][1] *= corr[0];
            O[i][2] *= corr[1]; O[i][3] *= corr[1];
        }

        // ---- PV single pass: P(16x64) x V^T(64x128)
#pragma unroll
        for (int c = 0; c < 4; c++) {
            uint32_t a[4];
            ldsm_x4(a, aP + c * 32);
#pragma unroll
            for (int np = 0; np < 8; np++) {
                uint32_t bf[4];
                ldsm_x4(bf, bV + c * 32 + np * (16 * 144));
                mma_fp16(O[np * 2 + 0], a, &bf[0]);
                mma_fp16(O[np * 2 + 1], a, &bf[2]);
            }
        }

        __syncthreads();   // all warps done reading buf before overwrite
        if (t + 2 < ntiles) ISSUE_T(t + 2, buf);
        asm volatile("cp.async.commit_group;" ::: "memory");
    }

    // ---- epilogue: normalize, write fp16 activations [B,S,E]
    float inv0 = 1.f / l[0], inv1 = 1.f / l[1];
#pragma unroll
    for (int nt = 0; nt < 16; nt++) {
        int col = h * 128 + nt * 8 + (lane & 3) * 2;
#pragma unroll
        for (int hh = 0; hh < 2; hh++) {
            float inv = hh ? inv1 : inv0;
            int srow = qbase + w * 16 + (lane >> 2) + hh * 8;
            size_t rb = ((size_t)(b * Ss + srow)) * GK + col;
            *(__half2*)(g_a_p + rb) =
                __floats2half2_rn(O[nt][hh * 2] * inv, O[nt][hh * 2 + 1] * inv);
        }
    }
}

// ---------------------------------------------------------------------------
extern "C" void kernel_launch(void* const* d_in, const int* in_sizes, int n_in,
                              void* d_out, int out_size)
{
    const float* hidden = (const float*)d_in[0];
    const float* wqkv   = (const float*)d_in[1];
    const float* wout   = (const float*)d_in[2];
    float* out = (float*)d_out;

    __half *pap, *pwqkv, *pwout, *pqp, *pkp, *pvt;
    cudaGetSymbolAddress((void**)&pap,   g_a_p);
    cudaGetSymbolAddress((void**)&pwqkv, g_wqkv_p);
    cudaGetSymbolAddress((void**)&pwout, g_wout_p);
    cudaGetSymbolAddress((void**)&pqp,   g_qp);
    cudaGetSymbolAddress((void**)&pkp,   g_kp);
    cudaGetSymbolAddress((void**)&pvt,   g_vt);

    cudaFuncSetAttribute(gemm_mma<0>, cudaFuncAttributeMaxDynamicSharedMemorySize,
                         GEMM_SMEM_BYTES);
    cudaFuncSetAttribute(gemm_mma<1>, cudaFuncAttributeMaxDynamicSharedMemorySize,
                         GEMM_SMEM_BYTES);
    cudaFuncSetAttribute(attn5, cudaFuncAttributeMaxDynamicSharedMemorySize,
                         ATTN_SMEM);

    // Rope table + fp16 packs
    rope_init<<<(Ss * 16) / 256, 256>>>();
    {
        int t4 = (3 * Ee * Ee) / 4;
        pack_fp16<<<(t4 + 1023) / 1024, 256>>>(wqkv, pwqkv, t4);
        t4 = (Ee * Ee) / 4;
        pack_fp16<<<(t4 + 1023) / 1024, 256>>>(wout, pwout, t4);
        t4 = (Bb * Ss * Ee) / 4;
        pack_fp16<<<(t4 + 1023) / 1024, 256>>>(hidden, pap, t4);
    }
    // 1) QKV projection + fused rope/scale/fp16 q,k,v^T epilogue
    {
        dim3 grid(3 * Ee / 128, Bb * Ss / 128);  // (48, 32)
        gemm_mma<1><<<grid, 256, GEMM_SMEM_BYTES>>>(pap, pwqkv, nullptr, 0);
    }
    // 2) Flash attention (fp16, Q-tile 64, 2 CTAs/SM) -> fp16 A in g_a_p
    {
        dim3 grid(Ss / 64, Hh, Bb);  // (32,16,2)
        attn5<<<grid, 128, ATTN_SMEM>>>(pqp, pkp, pvt);
    }
    // 3) Output projection
    {
        dim3 grid(Ee / 128, Bb * Ss / 128);  // (16, 32)
        gemm_mma<0><<<grid, 256, GEMM_SMEM_BYTES>>>(pap, pwout, out, Ee);
    }
}